// round 4
// baseline (speedup 1.0000x reference)
#include <cuda_runtime.h>
#include <cstdint>

#define NUM_ROWS 1000000
#define DIM 128
#define KPROBES 8

__global__ __launch_bounds__(256) void bloom_embed_kernel(
    const void* __restrict__ t_raw,
    const float* __restrict__ W,
    float* __restrict__ out,
    int n_tokens)
{
    int gwarp = (blockIdx.x * blockDim.x + threadIdx.x) >> 5;
    int lane  = threadIdx.x & 31;
    if (gwarp >= n_tokens) return;

    // --- inline dtype detection (int64 vs int32 token storage) ---
    // Tokens are uniform in [0, 1e9). If stored int64, the high 32 bits of
    // every 8-byte word are zero. If stored int32, each 8-byte word's high
    // half is another random token (zero w.p. ~1e-9). Lanes check the first
    // 4 words (lane & 3); all-hi-zero across the warp => int64.
    unsigned long long probe =
        ((const unsigned long long*)t_raw)[lane & 3];
    unsigned ball = __ballot_sync(0xffffffffu, (probe >> 32) == 0ULL);
    bool t_is_i64 = (ball == 0xffffffffu);

    // --- load token ---
    long long tok;
    if (t_is_i64)
        tok = ((const long long*)t_raw)[gwarp];
    else
        tok = (long long)((const int*)t_raw)[gwarp];

    // --- hash: lanes 0..7 (replicated x4) each compute one probe ---
    long long h = tok + (long long)(lane & 7);
    // Mueller hash with int64 wrapping semantics (arith shift, wrap-mul).
    h = (long long)(((unsigned long long)((h >> 16) ^ h)) * 73244475ULL);
    h = (long long)(((unsigned long long)((h >> 16) ^ h)) * 73244475ULL);
    h = (h >> 16) ^ h;
    long long m = h % (long long)NUM_ROWS;
    if (m < 0) m += NUM_ROWS;            // Python/jnp mod: sign of divisor
    int idx = (int)m;

    // broadcast the 8 probe indices to all lanes
    int rid[KPROBES];
#pragma unroll
    for (int k = 0; k < KPROBES; k++)
        rid[k] = __shfl_sync(0xffffffffu, idx, k);

    // --- front-batched gather: 8 independent LDG.128 per lane (MLP=8) ---
    const int col = lane * 4;
    float4 v[KPROBES];
#pragma unroll
    for (int k = 0; k < KPROBES; k++)
        v[k] = *reinterpret_cast<const float4*>(W + (size_t)rid[k] * DIM + col);

    float4 acc = v[0];
#pragma unroll
    for (int k = 1; k < KPROBES; k++) {
        acc.x += v[k].x; acc.y += v[k].y; acc.z += v[k].z; acc.w += v[k].w;
    }
    const float s = 1.0f / (float)KPROBES;
    acc.x *= s; acc.y *= s; acc.z *= s; acc.w *= s;

    *reinterpret_cast<float4*>(out + (size_t)gwarp * DIM + col) = acc;
}

extern "C" void kernel_launch(void* const* d_in, const int* in_sizes, int n_in,
                              void* d_out, int out_size)
{
    // Robust input selection: t is the small tensor (65,536 elements),
    // W is the big one (128,000,000 elements), regardless of metadata order.
    int ti = 0, wi = 1;
    if (n_in >= 2 && in_sizes[0] > in_sizes[1]) { ti = 1; wi = 0; }

    const void*  t = d_in[ti];
    const float* W = (const float*)d_in[wi];
    float*     out = (float*)d_out;

    int n_tokens = in_sizes[ti];                     // 65536

    int threads = 256;                               // 8 warps -> 8 tokens/block
    int blocks = (n_tokens * 32 + threads - 1) / threads;
    bloom_embed_kernel<<<blocks, threads>>>(t, W, out, n_tokens);
}

// round 5
// speedup vs baseline: 1.0514x; 1.0514x over previous
#include <cuda_runtime.h>
#include <cstdint>

#define NUM_ROWS 1000000
#define DIM 128
#define KPROBES 8

__global__ __launch_bounds__(256) void bloom_embed_kernel(
    const void* __restrict__ t_raw,
    const float* __restrict__ W,
    float* __restrict__ out,
    int n_tokens)
{
    int gwarp = (blockIdx.x * blockDim.x + threadIdx.x) >> 5;
    int lane  = threadIdx.x & 31;
    if (gwarp >= n_tokens) return;

    // --- inline dtype detection (int64 vs int32 token storage) ---
    // Tokens are uniform in [0, 1e9). If stored int64, the high 32 bits of
    // every 8-byte word are zero. If stored int32, each 8-byte word's high
    // half is another random token (zero w.p. ~1e-9). Lanes check the first
    // 4 words (lane & 3); all-hi-zero across the warp => int64.
    unsigned long long probe =
        ((const unsigned long long*)t_raw)[lane & 3];
    unsigned ball = __ballot_sync(0xffffffffu, (probe >> 32) == 0ULL);
    bool t_is_i64 = (ball == 0xffffffffu);

    // --- load token ---
    long long tok;
    if (t_is_i64)
        tok = ((const long long*)t_raw)[gwarp];
    else
        tok = (long long)((const int*)t_raw)[gwarp];

    // --- hash: lanes 0..7 (replicated x4) each compute one probe ---
    long long h = tok + (long long)(lane & 7);
    // Mueller hash with int64 wrapping semantics (arith shift, wrap-mul).
    h = (long long)(((unsigned long long)((h >> 16) ^ h)) * 73244475ULL);
    h = (long long)(((unsigned long long)((h >> 16) ^ h)) * 73244475ULL);
    h = (h >> 16) ^ h;
    long long m = h % (long long)NUM_ROWS;
    if (m < 0) m += NUM_ROWS;            // Python/jnp mod: sign of divisor
    int idx = (int)m;

    // broadcast the 8 probe indices to all lanes
    int rid[KPROBES];
#pragma unroll
    for (int k = 0; k < KPROBES; k++)
        rid[k] = __shfl_sync(0xffffffffu, idx, k);

    // --- front-batched gather: 8 independent LDG.128 per lane (MLP=8) ---
    // __ldcg: L2-only caching. W rows are random within 512 MB -> L1 hit
    // rate ~0; skipping L1 allocation avoids useless fills/evictions and
    // L1tex wavefront overhead.
    const int col = lane * 4;
    float4 v[KPROBES];
#pragma unroll
    for (int k = 0; k < KPROBES; k++)
        v[k] = __ldcg(reinterpret_cast<const float4*>(
                   W + (size_t)rid[k] * DIM + col));

    float4 acc = v[0];
#pragma unroll
    for (int k = 1; k < KPROBES; k++) {
        acc.x += v[k].x; acc.y += v[k].y; acc.z += v[k].z; acc.w += v[k].w;
    }
    const float s = 1.0f / (float)KPROBES;
    acc.x *= s; acc.y *= s; acc.z *= s; acc.w *= s;

    *reinterpret_cast<float4*>(out + (size_t)gwarp * DIM + col) = acc;
}

extern "C" void kernel_launch(void* const* d_in, const int* in_sizes, int n_in,
                              void* d_out, int out_size)
{
    // Robust input selection: t is the small tensor (65,536 elements),
    // W is the big one (128,000,000 elements), regardless of metadata order.
    int ti = 0, wi = 1;
    if (n_in >= 2 && in_sizes[0] > in_sizes[1]) { ti = 1; wi = 0; }

    const void*  t = d_in[ti];
    const float* W = (const float*)d_in[wi];
    float*     out = (float*)d_out;

    int n_tokens = in_sizes[ti];                     // 65536

    int threads = 256;                               // 8 warps -> 8 tokens/block
    int blocks = (n_tokens * 32 + threads - 1) / threads;
    bloom_embed_kernel<<<blocks, threads>>>(t, W, out, n_tokens);
}